// round 13
// baseline (speedup 1.0000x reference)
#include <cuda_runtime.h>
#include <cstdint>

// Shapes fixed by the problem: B=2, S=2048, E=1024, H=16, D=64.
static constexpr int E   = 1024;
static constexpr int NHD = 16;
static constexpr int HD  = 64;
static constexpr int B   = 2;
static constexpr int S   = 2048;
static constexpr int BS  = B * S;      // 4096 tokens
static constexpr int E3  = 3 * E;      // 3072

__device__ float g_qkv[(size_t)BS * E3];   // 48 MB
__device__ float g_xc[(size_t)BS * E];     // 16 MB  permuted x / permuted y
__device__ float g_wat[(size_t)E3 * E];    // 12 MB  w_attn^T, permuted
__device__ float g_wpt[(size_t)E * E];     //  4 MB  w_proj^T, permuted

// ---------------------------------------------------------------------------
// Helpers (mma.sync/cp.async are sm_80+ PTX: legal on compute_103; tcgen05
// is NOT — it needs the sm_103a target which this toolchain won't emit).
//
// GEMM operand layout ("quadset"): per row r, per 16-float k-group, chunk c
// holds quadset q = c ^ (r&3): elements k = q+4j at word j. One LDS.128 is a
// lane's m16n8k8 A/B fragment for 2 k-steps.
// ---------------------------------------------------------------------------
__device__ __forceinline__ uint32_t f2tf32(float f) {
    uint32_t u;
    asm("cvt.rna.tf32.f32 %0, %1;" : "=r"(u) : "f"(f));
    return u;
}
__device__ __forceinline__ float f2tf32f(float f) {
    return __uint_as_float(f2tf32(f));
}
__device__ __forceinline__ uint32_t smem_u32(const void* p) {
    uint32_t a;
    asm("{ .reg .u64 t; cvta.to.shared.u64 t, %1; cvt.u32.u64 %0, t; }"
        : "=r"(a) : "l"(p));
    return a;
}
__device__ __forceinline__ void cp16(uint32_t dst, const void* src) {
    asm volatile("cp.async.ca.shared.global [%0], [%1], 16;"
                 :: "r"(dst), "l"(src));
}
#define CP_COMMIT() asm volatile("cp.async.commit_group;" ::: "memory")
#define CP_WAIT2()  asm volatile("cp.async.wait_group 2;" ::: "memory")

// D = A(16x8, row) @ B(8x8, col) + C, tf32 in / f32 out.
__device__ __forceinline__ void mma_tf32(float* c, uint32_t a0, uint32_t a1,
                                         uint32_t a2, uint32_t a3,
                                         uint32_t b0, uint32_t b1) {
    asm volatile(
        "mma.sync.aligned.m16n8k8.row.col.f32.tf32.tf32.f32 "
        "{%0,%1,%2,%3}, {%4,%5,%6,%7}, {%8,%9}, {%0,%1,%2,%3};"
        : "+f"(c[0]), "+f"(c[1]), "+f"(c[2]), "+f"(c[3])
        : "r"(a0), "r"(a1), "r"(a2), "r"(a3), "r"(b0), "r"(b1));
}

// ---------------------------------------------------------------------------
// Pre-pass kernels (unchanged).
// ---------------------------------------------------------------------------
__global__ void permute_cvt_k(const float* __restrict__ in,
                              float* __restrict__ out, int nChunks, int Kf) {
    const int idx = blockIdx.x * blockDim.x + threadIdx.x;
    if (idx >= nChunks) return;
    const int cpr = Kf >> 2;
    const int r = idx / cpr;
    const int pos = idx - r * cpr;
    const int gbase = (pos >> 2) << 4;
    const int c = pos & 3;
    const int q = c ^ (r & 3);
    const float* src = in + (size_t)r * Kf + gbase + q;
    ((float4*)out)[idx] = make_float4(f2tf32f(src[0]), f2tf32f(src[4]),
                                      f2tf32f(src[8]), f2tf32f(src[12]));
}

__global__ void transpose_permute_k(const float* __restrict__ in,
                                    float* __restrict__ out, int R, int Cc) {
    __shared__ float t[32][33];
    const int c0 = blockIdx.x * 32, r0 = blockIdx.y * 32;
    #pragma unroll
    for (int j = 0; j < 4; j++) {
        const int r = threadIdx.y + j * 8;
        t[r][threadIdx.x] = in[(size_t)(r0 + r) * Cc + c0 + threadIdx.x];
    }
    __syncthreads();
    const int x = threadIdx.x;
    #pragma unroll
    for (int j = 0; j < 4; j++) {
        const int nl = threadIdx.y + j * 8;
        const int src_kk = (x & 16) | ((((x >> 2) & 3) ^ (nl & 3)) + ((x & 3) << 2));
        out[(size_t)(c0 + nl) * R + r0 + x] = f2tf32f(t[src_kk][nl]);
    }
}

// ---------------------------------------------------------------------------
// Tensor-core tf32 GEMM v4: 128 threads = 4 warps, warp tile 64x64,
// CTA tile 128x128, BK=16, 4-stage cp.async ring, 2 CTAs/SM.
// Smem traffic per HMMA drops 1.7x vs the 8-warp/64x32 version (L1 was the
// 77%-saturated resource): 16 LDS.128 per 64 HMMAs per warp.
// ---------------------------------------------------------------------------
static constexpr int GST_FLOATS = 2 * 128 * 16;             // 16 KB / stage
static constexpr int GEMM_SMEM  = 4 * GST_FLOATS * 4;       // 65536 B

__global__ __launch_bounds__(128, 2) void gemm_tc(
    const float* __restrict__ At, const float* __restrict__ Bt,
    float* __restrict__ C, int M, int N, int K)
{
    extern __shared__ float smf[];
    const uint32_t sbase = smem_u32(smf);

    const int tid  = threadIdx.x;
    const int wid  = tid >> 5;           // 0..3
    const int lane = tid & 31;
    const int g    = lane >> 2;
    const int tig  = lane & 3;
    const int m0   = (wid >> 1) * 64;    // warp m-origin (0 / 64)
    const int n0   = (wid & 1) * 64;     // warp n-origin (0 / 64)
    const int brow = blockIdx.y * 128;
    const int bcol = blockIdx.x * 128;

    // cp.async mapping: thread -> full row tid (4 chunks A + 4 chunks B).
    const float* gA = At + (size_t)(brow + tid) * K;
    const float* gB = Bt + (size_t)(bcol + tid) * K;
    const uint32_t dOff = (uint32_t)(tid * 64);

    float acc[4][8][4];
    #pragma unroll
    for (int mt = 0; mt < 4; mt++)
        #pragma unroll
        for (int nt = 0; nt < 8; nt++)
            #pragma unroll
            for (int i = 0; i < 4; i++) acc[mt][nt][i] = 0.f;

    const int nIter = K >> 4;

    #define G_ISSUE(it) do {                                                  \
        const uint32_t _d = sbase + ((it) & 3) * (GST_FLOATS * 4) + dOff;     \
        const float* _sa = gA + (it) * 16;                                    \
        const float* _sb = gB + (it) * 16;                                    \
        cp16(_d,           _sa);                                              \
        cp16(_d + 16,      _sa + 4);                                          \
        cp16(_d + 32,      _sa + 8);                                          \
        cp16(_d + 48,      _sa + 12);                                         \
        cp16(_d + 8192,      _sb);                                            \
        cp16(_d + 8192+16,   _sb + 4);                                        \
        cp16(_d + 8192+32,   _sb + 8);                                        \
        cp16(_d + 8192+48,   _sb + 12);                                       \
    } while (0)

    G_ISSUE(0); CP_COMMIT();
    G_ISSUE(1); CP_COMMIT();

    for (int it = 0; it < nIter; ++it) {
        if (it + 2 < nIter) G_ISSUE(it + 2);
        CP_COMMIT();
        CP_WAIT2();
        __syncthreads();

        const float* SA = smf + (it & 3) * GST_FLOATS;
        const float* SB = SA + 2048;

        // B fragments: one LDS.128 per 8-col tile (covers both k-steps).
        float4 bF[8];
        #pragma unroll
        for (int nt = 0; nt < 8; nt++) {
            const int n = n0 + nt * 8 + g;
            bF[nt] = *(const float4*)&SB[n * 16 + ((tig ^ (n & 3)) << 2)];
        }
        #pragma unroll
        for (int mt = 0; mt < 4; mt++) {
            const int ma = m0 + mt * 16 + g;
            const float4 a0v = *(const float4*)&SA[ma * 16 + ((tig ^ (ma & 3)) << 2)];
            const float4 a1v = *(const float4*)&SA[(ma + 8) * 16 + ((tig ^ (ma & 3)) << 2)];
            #pragma unroll
            for (int nt = 0; nt < 8; nt++)
                mma_tf32(acc[mt][nt],
                         __float_as_uint(a0v.x), __float_as_uint(a1v.x),
                         __float_as_uint(a0v.y), __float_as_uint(a1v.y),
                         __float_as_uint(bF[nt].x), __float_as_uint(bF[nt].y));
            #pragma unroll
            for (int nt = 0; nt < 8; nt++)
                mma_tf32(acc[mt][nt],
                         __float_as_uint(a0v.z), __float_as_uint(a1v.z),
                         __float_as_uint(a0v.w), __float_as_uint(a1v.w),
                         __float_as_uint(bF[nt].z), __float_as_uint(bF[nt].w));
        }
    }
    #undef G_ISSUE

    // Epilogue: c0,c1 -> (row g, cols 2tig,2tig+1); c2,c3 -> row g+8.
    #pragma unroll
    for (int mt = 0; mt < 4; mt++) {
        #pragma unroll
        for (int nt = 0; nt < 8; nt++) {
            const int r0 = brow + m0 + mt * 16 + g;
            const int cc = bcol + n0 + nt * 8 + 2 * tig;
            *(float2*)&C[(size_t)r0 * N + cc] =
                make_float2(acc[mt][nt][0], acc[mt][nt][1]);
            *(float2*)&C[(size_t)(r0 + 8) * N + cc] =
                make_float2(acc[mt][nt][2], acc[mt][nt][3]);
        }
    }
}

// ---------------------------------------------------------------------------
// Tensor-core flash attention (exact R10 build — best measured config).
//   Ks: [64 key rows][d quadset], row stride 80.
//   Vs: [64 key rows][d column-permuted], row stride 72.
// Epilogue writes y directly in the proj-GEMM's permuted tf32 layout.
// ---------------------------------------------------------------------------
static constexpr int ATT_Q_FLOATS = 128 * 72;   // Qs (reused as Ps)
static constexpr int ATT_K_FLOATS = 64 * 80;
static constexpr int ATT_V_FLOATS = 64 * 72;
static constexpr int ATT_SMEM_BYTES =
    (ATT_Q_FLOATS + ATT_K_FLOATS + ATT_V_FLOATS) * 4;     // 75,776 B

__global__ __launch_bounds__(256) void attn_mma(
    const float* __restrict__ qkv, float* __restrict__ yperm)
{
    extern __shared__ float sm[];
    float* Qs = sm;
    float* Ks = sm + ATT_Q_FLOATS;
    float* Vs = Ks + ATT_K_FLOATS;
    float* Ps = Qs;

    const int qt  = blockIdx.x;
    const int bh  = blockIdx.y;
    const int b   = bh >> 4;
    const int h   = bh & 15;
    const int q0  = qt * 128;
    const int tid = threadIdx.x;
    const int wid = tid >> 5;
    const int lane = tid & 31;
    const int g   = lane >> 2;
    const int tig = lane & 3;
    const int w16 = wid * 16;

    const float* base = qkv + (size_t)b * S * E3;
    const int hoff = h * HD;

    #pragma unroll
    for (int rep = 0; rep < 8; rep++) {
        const int idx = rep * 256 + tid;
        const int r = idx >> 4, d4 = (idx & 15) << 2;
        float4 v = *(const float4*)&base[(size_t)(q0 + r) * E3 + hoff + d4];
        *(float4*)&Qs[r * 72 + d4] = make_float4(
            f2tf32f(v.x * 0.125f), f2tf32f(v.y * 0.125f),
            f2tf32f(v.z * 0.125f), f2tf32f(v.w * 0.125f));
    }
    __syncthreads();

    uint32_t qa[8][4];
    #pragma unroll
    for (int kk = 0; kk < 8; kk++) {
        qa[kk][0] = __float_as_uint(Qs[(w16 + g)     * 72 + kk * 8 + tig]);
        qa[kk][1] = __float_as_uint(Qs[(w16 + g + 8) * 72 + kk * 8 + tig]);
        qa[kk][2] = __float_as_uint(Qs[(w16 + g)     * 72 + kk * 8 + tig + 4]);
        qa[kk][3] = __float_as_uint(Qs[(w16 + g + 8) * 72 + kk * 8 + tig + 4]);
    }
    __syncthreads();   // Qs now reusable as Ps

    float o[8][4];
    #pragma unroll
    for (int nt = 0; nt < 8; nt++)
        #pragma unroll
        for (int i = 0; i < 4; i++) o[nt][i] = 0.f;
    float m0v = -1e30f, m1v = -1e30f, l0 = 0.f, l1 = 0.f;

    const int row0g = q0 + w16 + g;
    const int nkt = 2 * qt + 2;

    for (int kt = 0; kt < nkt; kt++) {
        const int kbase = kt * 64;
        __syncthreads();
        #pragma unroll
        for (int rep = 0; rep < 4; rep++) {
            const int idx = rep * 256 + tid;
            const int r = idx >> 4, d4 = (idx & 15) << 2;
            const float* src = &base[(size_t)(kbase + r) * E3 + E + hoff + d4];
            float4 kv = *(const float4*)src;
            float4 vv = *(const float4*)(src + E);
            const float ka[4] = {kv.x, kv.y, kv.z, kv.w};
            const float va[4] = {vv.x, vv.y, vv.z, vv.w};
            const int kb = r * 80 + ((d4 >> 4) << 4) + ((d4 >> 2) & 3);
            const int vb = r * 72 + ((d4 >> 5) << 5) + ((d4 >> 3) & 3);
            #pragma unroll
            for (int e = 0; e < 4; e++) {
                Ks[kb + ((e ^ (r & 3)) << 2)] = f2tf32f(ka[e]);
                Vs[vb + (((d4 + e) & 7) << 2)] = f2tf32f(va[e]);
            }
        }
        __syncthreads();

        float s[8][4];
        #pragma unroll
        for (int nt = 0; nt < 8; nt++)
            #pragma unroll
            for (int i = 0; i < 4; i++) s[nt][i] = 0.f;

        #pragma unroll
        for (int gr = 0; gr < 4; gr++) {
            #pragma unroll
            for (int nt = 0; nt < 8; nt++) {
                const int n = nt * 8 + g;
                const float4 kf = *(const float4*)&Ks[n * 80 + gr * 16 +
                                                      ((tig ^ (n & 3)) << 2)];
                mma_tf32(s[nt], qa[2 * gr][0], qa[2 * gr][1],
                         qa[2 * gr][2], qa[2 * gr][3],
                         __float_as_uint(kf.x), __float_as_uint(kf.y));
                mma_tf32(s[nt], qa[2 * gr + 1][0], qa[2 * gr + 1][1],
                         qa[2 * gr + 1][2], qa[2 * gr + 1][3],
                         __float_as_uint(kf.z), __float_as_uint(kf.w));
            }
        }

        if (kt >= 2 * qt) {
            #pragma unroll
            for (int nt = 0; nt < 8; nt++) {
                const int key = kbase + nt * 8 + 2 * tig;
                if (key     > row0g)     s[nt][0] = -1e30f;
                if (key + 1 > row0g)     s[nt][1] = -1e30f;
                if (key     > row0g + 8) s[nt][2] = -1e30f;
                if (key + 1 > row0g + 8) s[nt][3] = -1e30f;
            }
        }

        float mx0 = -1e30f, mx1 = -1e30f;
        #pragma unroll
        for (int nt = 0; nt < 8; nt++) {
            mx0 = fmaxf(mx0, fmaxf(s[nt][0], s[nt][1]));
            mx1 = fmaxf(mx1, fmaxf(s[nt][2], s[nt][3]));
        }
        #pragma unroll
        for (int off = 1; off <= 2; off <<= 1) {
            mx0 = fmaxf(mx0, __shfl_xor_sync(0xffffffffu, mx0, off));
            mx1 = fmaxf(mx1, __shfl_xor_sync(0xffffffffu, mx1, off));
        }
        const float nm0 = fmaxf(m0v, mx0);
        const float nm1 = fmaxf(m1v, mx1);
        const float al0 = __expf(m0v - nm0);
        const float al1 = __expf(m1v - nm1);
        m0v = nm0; m1v = nm1;
        float rs0 = 0.f, rs1 = 0.f;
        #pragma unroll
        for (int nt = 0; nt < 8; nt++) {
            s[nt][0] = __expf(s[nt][0] - nm0); rs0 += s[nt][0];
            s[nt][1] = __expf(s[nt][1] - nm0); rs0 += s[nt][1];
            s[nt][2] = __expf(s[nt][2] - nm1); rs1 += s[nt][2];
            s[nt][3] = __expf(s[nt][3] - nm1); rs1 += s[nt][3];
        }
        #pragma unroll
        for (int off = 1; off <= 2; off <<= 1) {
            rs0 += __shfl_xor_sync(0xffffffffu, rs0, off);
            rs1 += __shfl_xor_sync(0xffffffffu, rs1, off);
        }
        l0 = l0 * al0 + rs0;
        l1 = l1 * al1 + rs1;
        #pragma unroll
        for (int nt = 0; nt < 8; nt++) {
            o[nt][0] *= al0; o[nt][1] *= al0;
            o[nt][2] *= al1; o[nt][3] *= al1;
        }

        #pragma unroll
        for (int nt = 0; nt < 8; nt++) {
            *(float2*)&Ps[(w16 + g) * 72 + nt * 8 + 2 * tig] = make_float2(
                f2tf32f(s[nt][0]), f2tf32f(s[nt][1]));
            *(float2*)&Ps[(w16 + g + 8) * 72 + nt * 8 + 2 * tig] = make_float2(
                f2tf32f(s[nt][2]), f2tf32f(s[nt][3]));
        }
        __syncwarp();

        #pragma unroll
        for (int kk = 0; kk < 8; kk++) {
            const uint32_t pa0 = __float_as_uint(Ps[(w16 + g)     * 72 + kk * 8 + tig]);
            const uint32_t pa1 = __float_as_uint(Ps[(w16 + g + 8) * 72 + kk * 8 + tig]);
            const uint32_t pa2 = __float_as_uint(Ps[(w16 + g)     * 72 + kk * 8 + tig + 4]);
            const uint32_t pa3 = __float_as_uint(Ps[(w16 + g + 8) * 72 + kk * 8 + tig + 4]);
            const float* r0p = &Vs[(kk * 8 + tig) * 72 + 4 * g];
            const float* r1p = r0p + 4 * 72;
            const float4 v0a = *(const float4*)r0p;
            const float4 v0b = *(const float4*)(r0p + 32);
            const float4 v1a = *(const float4*)r1p;
            const float4 v1b = *(const float4*)(r1p + 32);
            const float b0a[8] = {v0a.x, v0a.y, v0a.z, v0a.w,
                                  v0b.x, v0b.y, v0b.z, v0b.w};
            const float b1a[8] = {v1a.x, v1a.y, v1a.z, v1a.w,
                                  v1b.x, v1b.y, v1b.z, v1b.w};
            #pragma unroll
            for (int nt = 0; nt < 8; nt++)
                mma_tf32(o[nt], pa0, pa1, pa2, pa3,
                         __float_as_uint(b0a[nt]), __float_as_uint(b1a[nt]));
        }
        __syncwarp();
    }

    const float i0 = 1.f / l0;
    const float i1 = 1.f / l1;
    const int rg0 = b * S + q0 + w16 + g;      // (rg0+8)&3 == rg0&3
    #pragma unroll
    for (int nt = 0; nt < 8; nt++) {
        #pragma unroll
        for (int i = 0; i < 2; i++) {
            const int col = hoff + nt * 8 + 2 * tig + i;
            const size_t a0 = (size_t)rg0 * E + ((col >> 4) << 4) +
                              (((col & 3) ^ (rg0 & 3)) << 2) + ((col >> 2) & 3);
            yperm[a0]            = f2tf32f(o[nt][i]     * i0);
            yperm[a0 + 8 * E]    = f2tf32f(o[nt][i + 2] * i1);
        }
    }
}

// ---------------------------------------------------------------------------
extern "C" void kernel_launch(void* const* d_in, const int* in_sizes, int n_in,
                              void* d_out, int out_size)
{
    const float* x      = (const float*)d_in[0];
    const float* w_attn = (const float*)d_in[1];
    const float* w_proj = (const float*)d_in[2];
    float* out = (float*)d_out;

    float *qkv, *xc, *wat, *wpt;
    cudaGetSymbolAddress((void**)&qkv, g_qkv);
    cudaGetSymbolAddress((void**)&xc,  g_xc);
    cudaGetSymbolAddress((void**)&wat, g_wat);
    cudaGetSymbolAddress((void**)&wpt, g_wpt);

    cudaFuncSetAttribute(gemm_tc, cudaFuncAttributeMaxDynamicSharedMemorySize,
                         GEMM_SMEM);
    cudaFuncSetAttribute(attn_mma, cudaFuncAttributeMaxDynamicSharedMemorySize,
                         ATT_SMEM_BYTES);

    const int xChunks = BS * E / 4;

    // Pre-passes: cvt+permute x; transpose+cvt+permute weights.
    permute_cvt_k<<<(xChunks + 255) / 256, 256>>>(x, xc, xChunks, E);
    transpose_permute_k<<<dim3(E3 / 32, E / 32), dim3(32, 8)>>>(w_attn, wat, E, E3);
    transpose_permute_k<<<dim3(E / 32, E / 32), dim3(32, 8)>>>(w_proj, wpt, E, E);

    // 1) qkv = x @ w_attn   [4096, 3072]
    gemm_tc<<<dim3(E3 / 128, BS / 128), 128, GEMM_SMEM>>>(xc, wat, qkv, BS, E3, E);
    // 2) flash attention -> permuted y (written straight into proj-A layout)
    attn_mma<<<dim3(S / 128, B * NHD), 256, ATT_SMEM_BYTES>>>(qkv, xc);
    // 3) out = y @ w_proj   [4096, 1024]
    gemm_tc<<<dim3(E / 128, BS / 128), 128, GEMM_SMEM>>>(xc, wpt, out, BS, E, E);
}

// round 14
// speedup vs baseline: 1.2041x; 1.2041x over previous
#include <cuda_runtime.h>
#include <cstdint>

// Shapes fixed by the problem: B=2, S=2048, E=1024, H=16, D=64.
static constexpr int E   = 1024;
static constexpr int NHD = 16;
static constexpr int HD  = 64;
static constexpr int B   = 2;
static constexpr int S   = 2048;
static constexpr int BS  = B * S;      // 4096 tokens
static constexpr int E3  = 3 * E;      // 3072

__device__ float g_qkv[(size_t)BS * E3];   // 48 MB
__device__ float g_xc[(size_t)BS * E];     // 16 MB  permuted x / permuted y
__device__ float g_wat[(size_t)E3 * E];    // 12 MB  w_attn^T, permuted
__device__ float g_wpt[(size_t)E * E];     //  4 MB  w_proj^T, permuted

// ---------------------------------------------------------------------------
// Helpers (mma.sync/cp.async are sm_80+ PTX: legal on compute_103; tcgen05
// is NOT — it needs the sm_103a target which this toolchain won't emit).
// ---------------------------------------------------------------------------
__device__ __forceinline__ uint32_t f2tf32(float f) {
    uint32_t u;
    asm("cvt.rna.tf32.f32 %0, %1;" : "=r"(u) : "f"(f));
    return u;
}
__device__ __forceinline__ float f2tf32f(float f) {
    return __uint_as_float(f2tf32(f));
}
__device__ __forceinline__ uint32_t smem_u32(const void* p) {
    uint32_t a;
    asm("{ .reg .u64 t; cvta.to.shared.u64 t, %1; cvt.u32.u64 %0, t; }"
        : "=r"(a) : "l"(p));
    return a;
}
__device__ __forceinline__ void cp16(uint32_t dst, const void* src) {
    asm volatile("cp.async.ca.shared.global [%0], [%1], 16;"
                 :: "r"(dst), "l"(src));
}
#define CP_COMMIT() asm volatile("cp.async.commit_group;" ::: "memory")
#define CP_WAIT2()  asm volatile("cp.async.wait_group 2;" ::: "memory")

// D = A(16x8, row) @ B(8x8, col) + C, tf32 in / f32 out.
__device__ __forceinline__ void mma_tf32(float* c, uint32_t a0, uint32_t a1,
                                         uint32_t a2, uint32_t a3,
                                         uint32_t b0, uint32_t b1) {
    asm volatile(
        "mma.sync.aligned.m16n8k8.row.col.f32.tf32.tf32.f32 "
        "{%0,%1,%2,%3}, {%4,%5,%6,%7}, {%8,%9}, {%0,%1,%2,%3};"
        : "+f"(c[0]), "+f"(c[1]), "+f"(c[2]), "+f"(c[3])
        : "r"(a0), "r"(a1), "r"(a2), "r"(a3), "r"(b0), "r"(b1));
}

// ---------------------------------------------------------------------------
// Pre-pass kernels (unchanged).
// ---------------------------------------------------------------------------
__global__ void permute_cvt_k(const float* __restrict__ in,
                              float* __restrict__ out, int nChunks, int Kf) {
    const int idx = blockIdx.x * blockDim.x + threadIdx.x;
    if (idx >= nChunks) return;
    const int cpr = Kf >> 2;
    const int r = idx / cpr;
    const int pos = idx - r * cpr;
    const int gbase = (pos >> 2) << 4;
    const int c = pos & 3;
    const int q = c ^ (r & 3);
    const float* src = in + (size_t)r * Kf + gbase + q;
    ((float4*)out)[idx] = make_float4(f2tf32f(src[0]), f2tf32f(src[4]),
                                      f2tf32f(src[8]), f2tf32f(src[12]));
}

__global__ void transpose_permute_k(const float* __restrict__ in,
                                    float* __restrict__ out, int R, int Cc) {
    __shared__ float t[32][33];
    const int c0 = blockIdx.x * 32, r0 = blockIdx.y * 32;
    #pragma unroll
    for (int j = 0; j < 4; j++) {
        const int r = threadIdx.y + j * 8;
        t[r][threadIdx.x] = in[(size_t)(r0 + r) * Cc + c0 + threadIdx.x];
    }
    __syncthreads();
    const int x = threadIdx.x;
    #pragma unroll
    for (int j = 0; j < 4; j++) {
        const int nl = threadIdx.y + j * 8;
        const int src_kk = (x & 16) | ((((x >> 2) & 3) ^ (nl & 3)) + ((x & 3) << 2));
        out[(size_t)(c0 + nl) * R + r0 + x] = f2tf32f(t[src_kk][nl]);
    }
}

// ---------------------------------------------------------------------------
// Tensor-core tf32 GEMM (EXACT R10 build: 256 thr, BK=16, 4-stage cp.async,
// 2 CTAs/SM — empirically the best of all tried gemm variants).
// ---------------------------------------------------------------------------
static constexpr int GST_FLOATS = 2 * 128 * 16;             // 16 KB
static constexpr int GEMM_SMEM  = 4 * GST_FLOATS * 4;       // 65536 B

__global__ __launch_bounds__(256, 2) void gemm_tc(
    const float* __restrict__ At, const float* __restrict__ Bt,
    float* __restrict__ C, int M, int N, int K)
{
    extern __shared__ float smf[];
    const uint32_t sbase = smem_u32(smf);

    const int tid  = threadIdx.x;
    const int wid  = tid >> 5;
    const int lane = tid & 31;
    const int g    = lane >> 2;
    const int tig  = lane & 3;
    const int m0   = (wid >> 2) * 64;
    const int n0   = (wid & 3) * 32;
    const int brow = blockIdx.y * 128;
    const int bcol = blockIdx.x * 128;

    const int lr = tid >> 1;
    const int lc = (tid & 1) * 2;
    const float* gA = At + (size_t)(brow + lr) * K + lc * 4;
    const float* gB = Bt + (size_t)(bcol + lr) * K + lc * 4;
    const uint32_t dOff = (uint32_t)(lr * 64 + lc * 16);

    float acc[4][4][4];
    #pragma unroll
    for (int mt = 0; mt < 4; mt++)
        #pragma unroll
        for (int nt = 0; nt < 4; nt++)
            #pragma unroll
            for (int i = 0; i < 4; i++) acc[mt][nt][i] = 0.f;

    const int nIter = K >> 4;

    #define G_ISSUE(it) do {                                                  \
        const uint32_t _dA = sbase + ((it) & 3) * (GST_FLOATS * 4) + dOff;    \
        const float* _sa = gA + (it) * 16;                                    \
        const float* _sb = gB + (it) * 16;                                    \
        cp16(_dA,        _sa);                                                \
        cp16(_dA + 16,   _sa + 4);                                            \
        cp16(_dA + 8192, _sb);                                                \
        cp16(_dA + 8208, _sb + 4);                                            \
    } while (0)

    G_ISSUE(0); CP_COMMIT();
    G_ISSUE(1); CP_COMMIT();

    for (int it = 0; it < nIter; ++it) {
        if (it + 2 < nIter) G_ISSUE(it + 2);
        CP_COMMIT();
        CP_WAIT2();
        __syncthreads();

        const float* SA = smf + (it & 3) * GST_FLOATS;
        const float* SB = SA + 2048;

        float4 bF[4];
        #pragma unroll
        for (int nt = 0; nt < 4; nt++) {
            const int n = n0 + nt * 8 + g;
            bF[nt] = *(const float4*)&SB[n * 16 + ((tig ^ (n & 3)) << 2)];
        }
        #pragma unroll
        for (int mt = 0; mt < 4; mt++) {
            const int ma = m0 + mt * 16 + g;
            const float4 a0v = *(const float4*)&SA[ma * 16 + ((tig ^ (ma & 3)) << 2)];
            const float4 a1v = *(const float4*)&SA[(ma + 8) * 16 + ((tig ^ (ma & 3)) << 2)];
            #pragma unroll
            for (int nt = 0; nt < 4; nt++)
                mma_tf32(acc[mt][nt],
                         __float_as_uint(a0v.x), __float_as_uint(a1v.x),
                         __float_as_uint(a0v.y), __float_as_uint(a1v.y),
                         __float_as_uint(bF[nt].x), __float_as_uint(bF[nt].y));
            #pragma unroll
            for (int nt = 0; nt < 4; nt++)
                mma_tf32(acc[mt][nt],
                         __float_as_uint(a0v.z), __float_as_uint(a1v.z),
                         __float_as_uint(a0v.w), __float_as_uint(a1v.w),
                         __float_as_uint(bF[nt].z), __float_as_uint(bF[nt].w));
        }
    }
    #undef G_ISSUE

    #pragma unroll
    for (int mt = 0; mt < 4; mt++) {
        #pragma unroll
        for (int nt = 0; nt < 4; nt++) {
            const int r0 = brow + m0 + mt * 16 + g;
            const int cc = bcol + n0 + nt * 8 + 2 * tig;
            *(float2*)&C[(size_t)r0 * N + cc] =
                make_float2(acc[mt][nt][0], acc[mt][nt][1]);
            *(float2*)&C[(size_t)(r0 + 8) * N + cc] =
                make_float2(acc[mt][nt][2], acc[mt][nt][3]);
        }
    }
}

// ---------------------------------------------------------------------------
// Tensor-core flash attention (R10 math) + software-pipelined K/V staging:
// tile kt+1's K/V are LDG-prefetched into registers during tile kt's compute,
// so the staging phase is pure cvt+STS (no exposed gmem latency).
// ---------------------------------------------------------------------------
static constexpr int ATT_Q_FLOATS = 128 * 72;   // Qs (reused as Ps)
static constexpr int ATT_K_FLOATS = 64 * 80;
static constexpr int ATT_V_FLOATS = 64 * 72;
static constexpr int ATT_SMEM_BYTES =
    (ATT_Q_FLOATS + ATT_K_FLOATS + ATT_V_FLOATS) * 4;     // 75,776 B

__global__ __launch_bounds__(256) void attn_mma(
    const float* __restrict__ qkv, float* __restrict__ yperm)
{
    extern __shared__ float sm[];
    float* Qs = sm;
    float* Ks = sm + ATT_Q_FLOATS;
    float* Vs = Ks + ATT_K_FLOATS;
    float* Ps = Qs;

    const int qt  = blockIdx.x;
    const int bh  = blockIdx.y;
    const int b   = bh >> 4;
    const int h   = bh & 15;
    const int q0  = qt * 128;
    const int tid = threadIdx.x;
    const int wid = tid >> 5;
    const int lane = tid & 31;
    const int g   = lane >> 2;
    const int tig = lane & 3;
    const int w16 = wid * 16;

    const float* base = qkv + (size_t)b * S * E3;
    const int hoff = h * HD;

    // Per-thread staging coordinates (fixed across tiles).
    const int st_r  = tid >> 4;            // rows tid>>4, +16, +32, +48
    const int st_d4 = (tid & 15) << 2;
    const float* kvsrc = &base[(size_t)st_r * E3 + E + hoff + st_d4];

    // Stage Q (scale folded, tf32), plain [row][72] layout.
    #pragma unroll
    for (int rep = 0; rep < 8; rep++) {
        const int idx = rep * 256 + tid;
        const int r = idx >> 4, d4 = (idx & 15) << 2;
        float4 v = *(const float4*)&base[(size_t)(q0 + r) * E3 + hoff + d4];
        *(float4*)&Qs[r * 72 + d4] = make_float4(
            f2tf32f(v.x * 0.125f), f2tf32f(v.y * 0.125f),
            f2tf32f(v.z * 0.125f), f2tf32f(v.w * 0.125f));
    }
    __syncthreads();

    uint32_t qa[8][4];
    #pragma unroll
    for (int kk = 0; kk < 8; kk++) {
        qa[kk][0] = __float_as_uint(Qs[(w16 + g)     * 72 + kk * 8 + tig]);
        qa[kk][1] = __float_as_uint(Qs[(w16 + g + 8) * 72 + kk * 8 + tig]);
        qa[kk][2] = __float_as_uint(Qs[(w16 + g)     * 72 + kk * 8 + tig + 4]);
        qa[kk][3] = __float_as_uint(Qs[(w16 + g + 8) * 72 + kk * 8 + tig + 4]);
    }
    __syncthreads();   // Qs now reusable as Ps

    float o[8][4];
    #pragma unroll
    for (int nt = 0; nt < 8; nt++)
        #pragma unroll
        for (int i = 0; i < 4; i++) o[nt][i] = 0.f;
    float m0v = -1e30f, m1v = -1e30f, l0 = 0.f, l1 = 0.f;

    const int row0g = q0 + w16 + g;
    const int nkt = 2 * qt + 2;

    // Prefetch tile 0 K/V into registers.
    float4 kvr[4], vvr[4];
    #pragma unroll
    for (int rep = 0; rep < 4; rep++) {
        const float* src = kvsrc + (size_t)(rep * 16) * E3;
        kvr[rep] = *(const float4*)src;
        vvr[rep] = *(const float4*)(src + E);
    }

    for (int kt = 0; kt < nkt; kt++) {
        const int kbase = kt * 64;
        __syncthreads();   // prior compute's Ks/Vs reads complete

        // Staging: pure cvt + scatter-STS from prefetched registers.
        #pragma unroll
        for (int rep = 0; rep < 4; rep++) {
            const int r = st_r + rep * 16;
            const int d4 = st_d4;
            const float ka[4] = {kvr[rep].x, kvr[rep].y, kvr[rep].z, kvr[rep].w};
            const float va[4] = {vvr[rep].x, vvr[rep].y, vvr[rep].z, vvr[rep].w};
            const int kb = r * 80 + ((d4 >> 4) << 4) + ((d4 >> 2) & 3);
            const int vb = r * 72 + ((d4 >> 5) << 5) + ((d4 >> 3) & 3);
            #pragma unroll
            for (int e = 0; e < 4; e++) {
                Ks[kb + ((e ^ (r & 3)) << 2)] = f2tf32f(ka[e]);
                Vs[vb + (((d4 + e) & 7) << 2)] = f2tf32f(va[e]);
            }
        }
        __syncthreads();   // publish Ks/Vs

        // Prefetch tile kt+1 (latency hidden behind the compute below).
        if (kt + 1 < nkt) {
            const float* nsrc = kvsrc + (size_t)((kt + 1) * 64) * E3;
            #pragma unroll
            for (int rep = 0; rep < 4; rep++) {
                const float* src = nsrc + (size_t)(rep * 16) * E3;
                kvr[rep] = *(const float4*)src;
                vvr[rep] = *(const float4*)(src + E);
            }
        }

        // S = Q @ K^T
        float s[8][4];
        #pragma unroll
        for (int nt = 0; nt < 8; nt++)
            #pragma unroll
            for (int i = 0; i < 4; i++) s[nt][i] = 0.f;

        #pragma unroll
        for (int gr = 0; gr < 4; gr++) {
            #pragma unroll
            for (int nt = 0; nt < 8; nt++) {
                const int n = nt * 8 + g;
                const float4 kf = *(const float4*)&Ks[n * 80 + gr * 16 +
                                                      ((tig ^ (n & 3)) << 2)];
                mma_tf32(s[nt], qa[2 * gr][0], qa[2 * gr][1],
                         qa[2 * gr][2], qa[2 * gr][3],
                         __float_as_uint(kf.x), __float_as_uint(kf.y));
                mma_tf32(s[nt], qa[2 * gr + 1][0], qa[2 * gr + 1][1],
                         qa[2 * gr + 1][2], qa[2 * gr + 1][3],
                         __float_as_uint(kf.z), __float_as_uint(kf.w));
            }
        }

        if (kt >= 2 * qt) {
            #pragma unroll
            for (int nt = 0; nt < 8; nt++) {
                const int key = kbase + nt * 8 + 2 * tig;
                if (key     > row0g)     s[nt][0] = -1e30f;
                if (key + 1 > row0g)     s[nt][1] = -1e30f;
                if (key     > row0g + 8) s[nt][2] = -1e30f;
                if (key + 1 > row0g + 8) s[nt][3] = -1e30f;
            }
        }

        float mx0 = -1e30f, mx1 = -1e30f;
        #pragma unroll
        for (int nt = 0; nt < 8; nt++) {
            mx0 = fmaxf(mx0, fmaxf(s[nt][0], s[nt][1]));
            mx1 = fmaxf(mx1, fmaxf(s[nt][2], s[nt][3]));
        }
        #pragma unroll
        for (int off = 1; off <= 2; off <<= 1) {
            mx0 = fmaxf(mx0, __shfl_xor_sync(0xffffffffu, mx0, off));
            mx1 = fmaxf(mx1, __shfl_xor_sync(0xffffffffu, mx1, off));
        }
        const float nm0 = fmaxf(m0v, mx0);
        const float nm1 = fmaxf(m1v, mx1);
        const float al0 = __expf(m0v - nm0);
        const float al1 = __expf(m1v - nm1);
        m0v = nm0; m1v = nm1;
        float rs0 = 0.f, rs1 = 0.f;
        #pragma unroll
        for (int nt = 0; nt < 8; nt++) {
            s[nt][0] = __expf(s[nt][0] - nm0); rs0 += s[nt][0];
            s[nt][1] = __expf(s[nt][1] - nm0); rs0 += s[nt][1];
            s[nt][2] = __expf(s[nt][2] - nm1); rs1 += s[nt][2];
            s[nt][3] = __expf(s[nt][3] - nm1); rs1 += s[nt][3];
        }
        #pragma unroll
        for (int off = 1; off <= 2; off <<= 1) {
            rs0 += __shfl_xor_sync(0xffffffffu, rs0, off);
            rs1 += __shfl_xor_sync(0xffffffffu, rs1, off);
        }
        l0 = l0 * al0 + rs0;
        l1 = l1 * al1 + rs1;
        #pragma unroll
        for (int nt = 0; nt < 8; nt++) {
            o[nt][0] *= al0; o[nt][1] *= al0;
            o[nt][2] *= al1; o[nt][3] *= al1;
        }

        #pragma unroll
        for (int nt = 0; nt < 8; nt++) {
            *(float2*)&Ps[(w16 + g) * 72 + nt * 8 + 2 * tig] = make_float2(
                f2tf32f(s[nt][0]), f2tf32f(s[nt][1]));
            *(float2*)&Ps[(w16 + g + 8) * 72 + nt * 8 + 2 * tig] = make_float2(
                f2tf32f(s[nt][2]), f2tf32f(s[nt][3]));
        }
        __syncwarp();

        #pragma unroll
        for (int kk = 0; kk < 8; kk++) {
            const uint32_t pa0 = __float_as_uint(Ps[(w16 + g)     * 72 + kk * 8 + tig]);
            const uint32_t pa1 = __float_as_uint(Ps[(w16 + g + 8) * 72 + kk * 8 + tig]);
            const uint32_t pa2 = __float_as_uint(Ps[(w16 + g)     * 72 + kk * 8 + tig + 4]);
            const uint32_t pa3 = __float_as_uint(Ps[(w16 + g + 8) * 72 + kk * 8 + tig + 4]);
            const float* r0p = &Vs[(kk * 8 + tig) * 72 + 4 * g];
            const float* r1p = r0p + 4 * 72;
            const float4 v0a = *(const float4*)r0p;
            const float4 v0b = *(const float4*)(r0p + 32);
            const float4 v1a = *(const float4*)r1p;
            const float4 v1b = *(const float4*)(r1p + 32);
            const float b0a[8] = {v0a.x, v0a.y, v0a.z, v0a.w,
                                  v0b.x, v0b.y, v0b.z, v0b.w};
            const float b1a[8] = {v1a.x, v1a.y, v1a.z, v1a.w,
                                  v1b.x, v1b.y, v1b.z, v1b.w};
            #pragma unroll
            for (int nt = 0; nt < 8; nt++)
                mma_tf32(o[nt], pa0, pa1, pa2, pa3,
                         __float_as_uint(b0a[nt]), __float_as_uint(b1a[nt]));
        }
        __syncwarp();
    }

    const float i0 = 1.f / l0;
    const float i1 = 1.f / l1;
    const int rg0 = b * S + q0 + w16 + g;      // (rg0+8)&3 == rg0&3
    #pragma unroll
    for (int nt = 0; nt < 8; nt++) {
        #pragma unroll
        for (int i = 0; i < 2; i++) {
            const int col = hoff + nt * 8 + 2 * tig + i;
            const size_t a0 = (size_t)rg0 * E + ((col >> 4) << 4) +
                              (((col & 3) ^ (rg0 & 3)) << 2) + ((col >> 2) & 3);
            yperm[a0]            = f2tf32f(o[nt][i]     * i0);
            yperm[a0 + 8 * E]    = f2tf32f(o[nt][i + 2] * i1);
        }
    }
}

// ---------------------------------------------------------------------------
extern "C" void kernel_launch(void* const* d_in, const int* in_sizes, int n_in,
                              void* d_out, int out_size)
{
    const float* x      = (const float*)d_in[0];
    const float* w_attn = (const float*)d_in[1];
    const float* w_proj = (const float*)d_in[2];
    float* out = (float*)d_out;

    float *qkv, *xc, *wat, *wpt;
    cudaGetSymbolAddress((void**)&qkv, g_qkv);
    cudaGetSymbolAddress((void**)&xc,  g_xc);
    cudaGetSymbolAddress((void**)&wat, g_wat);
    cudaGetSymbolAddress((void**)&wpt, g_wpt);

    cudaFuncSetAttribute(gemm_tc, cudaFuncAttributeMaxDynamicSharedMemorySize,
                         GEMM_SMEM);
    cudaFuncSetAttribute(attn_mma, cudaFuncAttributeMaxDynamicSharedMemorySize,
                         ATT_SMEM_BYTES);

    const int xChunks = BS * E / 4;

    // Pre-passes: cvt+permute x; transpose+cvt+permute weights.
    permute_cvt_k<<<(xChunks + 255) / 256, 256>>>(x, xc, xChunks, E);
    transpose_permute_k<<<dim3(E3 / 32, E / 32), dim3(32, 8)>>>(w_attn, wat, E, E3);
    transpose_permute_k<<<dim3(E / 32, E / 32), dim3(32, 8)>>>(w_proj, wpt, E, E);

    // 1) qkv = x @ w_attn   [4096, 3072]
    gemm_tc<<<dim3(E3 / 128, BS / 128), 256, GEMM_SMEM>>>(xc, wat, qkv, BS, E3, E);
    // 2) flash attention -> permuted y (written straight into proj-A layout)
    attn_mma<<<dim3(S / 128, B * NHD), 256, ATT_SMEM_BYTES>>>(qkv, xc);
    // 3) out = y @ w_proj   [4096, 1024]
    gemm_tc<<<dim3(E / 128, BS / 128), 256, GEMM_SMEM>>>(xc, wpt, out, BS, E, E);
}